// round 11
// baseline (speedup 1.0000x reference)
#include <cuda_runtime.h>
#include <cuda_bf16.h>
#include <cstdint>
#include <math.h>

// Problem constants (fixed by setup_inputs)
#define BB 64
#define TT 1024
#define VV 512
#define SS 128
#define LL 257            // 2*S + 1 extended states
#define GSTRIDE 132       // padded row stride for gathered log-probs
#define NEGF (-1e30f)
#define PF   6            // cp.async prefetch depth (rows ahead)
#define RING 8            // ring slots (power of 2, > PF+1)
#define LOG2E 1.4426950408889634f
#define LN2   0.6931471805599453f

// Scratch: gathered log2-probs  g[b,t,j] = (logits[b,t,sym_j] - lse(b,t)) * log2(e)
// j=0 -> blank(0), j=1..128 -> target symbols.
__device__ float g_lp[(size_t)BB * TT * GSTRIDE];   // ~34.6 MB
__device__ float g_partial[BB];

// ---------------------------------------------------------------------------
// Phase 1: per-row logsumexp over V=512 + gather of 129 symbol log-probs,
// pre-scaled to log2 domain. One warp per (b,t) row. (~22us, near HBM bound.)
// ---------------------------------------------------------------------------
__global__ __launch_bounds__(256) void lse_gather_kernel(
    const float* __restrict__ logits,      // [B,T,V]
    const int*   __restrict__ in_len,      // [B]
    const int*   __restrict__ tgt)         // [B,S]
{
    int gwarp = (blockIdx.x * blockDim.x + threadIdx.x) >> 5;
    int lane  = threadIdx.x & 31;
    if (gwarp >= BB * TT) return;

    int b = gwarp >> 10;          // / TT
    int t = gwarp & (TT - 1);
    if (t >= in_len[b]) return;   // frames past utterance length are never read

    const float4* row4 = (const float4*)(logits + (size_t)gwarp * VV);

    float4 v[4];
    float mx = -INFINITY;
#pragma unroll
    for (int i = 0; i < 4; i++) {
        v[i] = row4[lane + 32 * i];
        mx = fmaxf(mx, fmaxf(fmaxf(v[i].x, v[i].y), fmaxf(v[i].z, v[i].w)));
    }
#pragma unroll
    for (int o = 16; o > 0; o >>= 1)
        mx = fmaxf(mx, __shfl_xor_sync(0xFFFFFFFFu, mx, o));

    float sum = 0.f;
#pragma unroll
    for (int i = 0; i < 4; i++) {
        sum += __expf(v[i].x - mx) + __expf(v[i].y - mx) +
               __expf(v[i].z - mx) + __expf(v[i].w - mx);
    }
#pragma unroll
    for (int o = 16; o > 0; o >>= 1)
        sum += __shfl_xor_sync(0xFFFFFFFFu, sum, o);

    float lse = mx + __logf(sum);

    const float* rowf = logits + (size_t)gwarp * VV;
    const int*   tb   = tgt + b * SS;
    float*       out  = g_lp + (size_t)gwarp * GSTRIDE;
#pragma unroll
    for (int j = lane; j < SS + 1; j += 32) {
        int sym = (j == 0) ? 0 : tb[j - 1];
        out[j] = (rowf[sym] - lse) * LOG2E;   // log2 domain
    }
}

// ---------------------------------------------------------------------------
// Phase 2: CTC alpha recursion in log2 domain.
// One CTA per batch, 160 threads. Thread i<128 owns state pair (2i, 2i+1);
// thread 128 owns state 256. Both updates need only o_{i-1} from the left:
//   new e_i = lse2(e_i, o_{i-1}) + lp_blank
//   new o_i = lse3(o_i, e_i, skip ? o_{i-1} : -inf) + lp_label(i)
// => one shfl_up per step; 4 floats cross warp boundaries via shared
// (double-buffered). lp rows staged PF ahead by cp.async ring.
// ---------------------------------------------------------------------------
__device__ __forceinline__ void cp_async_f32(unsigned int dst_smem, const float* src)
{
    asm volatile("cp.async.ca.shared.global [%0], [%1], 4;\n"
                 :: "r"(dst_smem), "l"(src));
}
__device__ __forceinline__ void cp_commit()
{
    asm volatile("cp.async.commit_group;\n");
}
__device__ __forceinline__ void cp_wait_pf()
{
    asm volatile("cp.async.wait_group %0;\n" :: "n"(PF));
}
__device__ __forceinline__ float ex2f(float x)
{
    float r; asm("ex2.approx.ftz.f32 %0, %1;" : "=f"(r) : "f"(x)); return r;
}
__device__ __forceinline__ float lg2f(float x)
{
    float r; asm("lg2.approx.ftz.f32 %0, %1;" : "=f"(r) : "f"(x)); return r;
}

__global__ __launch_bounds__(160) void ctc_alpha_kernel(
    const int* __restrict__ in_len,
    const int* __restrict__ tgt,
    const int* __restrict__ tgt_len)
{
    const int b    = blockIdx.x;
    const int tid  = threadIdx.x;
    const int wid  = tid >> 5;
    const int lane = tid & 31;
    const bool pairT  = (tid < 128);           // owns states 2*tid, 2*tid+1
    const bool lastT  = (tid == 128);          // owns state 256 (even/blank)
    const bool compT  = pairT || lastT;
    const bool loader = (tid <= SS);           // threads 0..128 stage lp cols

    __shared__ float shlp[RING][GSTRIDE];
    __shared__ float sh_ex[2][4];              // warp-boundary o values
    __shared__ float fin[LL];

    // skip for odd state 2i+1 (label index i): i>=1 && tgt[i]!=tgt[i-1]
    bool skip = false;
    if (pairT && tid >= 1)
        skip = (tgt[b * SS + tid] != tgt[b * SS + tid - 1]);

    const float* grow = g_lp + (size_t)b * TT * GSTRIDE;
    const int len = in_len[b];                 // >= 512 for this problem

    unsigned int slotb = 0;
    if (loader)
        slotb = (unsigned int)__cvta_generic_to_shared(&shlp[0][tid]);

    // Prologue: stage rows 1..PF (one commit-group per row)
#pragma unroll
    for (int r = 1; r <= PF; r++) {
        if (loader)
            cp_async_f32(slotb + (unsigned int)(r & (RING - 1)) * (GSTRIDE * 4),
                         grow + (size_t)r * GSTRIDE + tid);
        cp_commit();
    }

    // t = 0 init (log2 domain, grow already scaled)
    float e = NEGF, o = NEGF;
    if (tid == 0) { e = grow[0]; o = grow[1]; }

    int buf = 0;
    for (int t = 1; t < len; t++) {
        int r = t + PF;
        if (loader && r < len)
            cp_async_f32(slotb + (unsigned int)(r & (RING - 1)) * (GSTRIDE * 4),
                         grow + (size_t)r * GSTRIDE + tid);
        cp_commit();                            // exactly one group per iter

        if (lane == 31 && wid < 4) sh_ex[buf][wid] = o;
        cp_wait_pf();                           // row t complete (issuers)
        __syncthreads();                        // ...visible to all

        float op = __shfl_up_sync(0xFFFFFFFFu, o, 1);
        if (lane == 0) op = (wid == 0) ? NEGF : sh_ex[buf][wid - 1];

        if (compT) {
            float lpb = shlp[t & (RING - 1)][0];
            // even state: lse2(e, op) + blank lp
            float m1 = fmaxf(e, op);
            float ne = m1 + lg2f(ex2f(e - m1) + ex2f(op - m1)) + lpb;
            if (pairT) {
                float lpl = shlp[t & (RING - 1)][tid + 1];
                float a2  = skip ? op : NEGF;
                float m2  = fmaxf(o, fmaxf(e, a2));
                o = m2 + lg2f(ex2f(o - m2) + ex2f(e - m2) + ex2f(a2 - m2)) + lpl;
            }
            e = ne;
        }
        buf ^= 1;
    }

    if (compT) {
        fin[2 * tid] = e;
        if (pairT) fin[2 * tid + 1] = o;
    }
    __syncthreads();

    if (tid == 0) {
        int ee = 2 * tgt_len[b];
        float x = fin[ee];           // alpha[2*tl]
        float y = fin[ee - 1];       // alpha[2*tl - 1]
        float m = fmaxf(x, y);
        float ll2 = m + lg2f(ex2f(x - m) + ex2f(y - m));
        float loss = -ll2 * LN2;     // back to natural log
        if (loss > 1e29f) loss = 0.f;    // zero_infinity
        g_partial[b] = loss;
    }
}

// ---------------------------------------------------------------------------
// Phase 3: deterministic reduction of 64 per-batch losses -> scalar
// ---------------------------------------------------------------------------
__global__ void reduce_loss_kernel(float* __restrict__ out)
{
    int l = threadIdx.x;                   // 32 threads
    float v = g_partial[l] + g_partial[l + 32];
#pragma unroll
    for (int o = 16; o > 0; o >>= 1)
        v += __shfl_xor_sync(0xFFFFFFFFu, v, o);
    if (l == 0) out[0] = v;
}

// ---------------------------------------------------------------------------
extern "C" void kernel_launch(void* const* d_in, const int* in_sizes, int n_in,
                              void* d_out, int out_size)
{
    const float* logits  = (const float*)d_in[0];   // [B,T,V] fp32
    const int*   in_len  = (const int*)d_in[1];     // [B]
    const int*   tgt     = (const int*)d_in[2];     // [B,S]
    const int*   tgt_len = (const int*)d_in[3];     // [B]
    float*       out     = (float*)d_out;

    lse_gather_kernel<<<(BB * TT) / 8, 256>>>(logits, in_len, tgt);
    ctc_alpha_kernel<<<BB, 160>>>(in_len, tgt, tgt_len);
    reduce_loss_kernel<<<1, 32>>>(out);
}